// round 8
// baseline (speedup 1.0000x reference)
#include <cuda_runtime.h>
#include <cstdint>
#include <math.h>

#define BATCH 512
#define FEAT  512
#define NSPLIT 255
#define NNODE  511
#define NC     21
#define NBLK   128
#define NTHR   512

typedef unsigned long long ull;

// ---- persistent scratch (no allocation allowed) ----
__device__ float4 d_wt2[128 * 256];          // [f/4][s] interleaved-transposed W
__device__ float  d_part[2][BATCH][NSPLIT];  // per-K-half partial GEMM
__device__ float  d_qrelu[BATCH * NNODE];    // max(q_node,0), row-major [b][n]
__device__ float4 d_qT4[NNODE * 128];        // raw q_node transposed [n][b/4]
__device__ float  d_ga[NNODE * NC];
__device__ float  d_anode[NNODE];
__device__ unsigned g_ctr[8];
__device__ unsigned g_rel[8];

// Software grid barrier: all NBLK blocks co-resident (128 blocks, 1/SM, 148 SMs).
__device__ __forceinline__ void grid_bar(int i) {
    __threadfence();
    __syncthreads();
    if (threadIdx.x == 0) {
        volatile unsigned* rel = &g_rel[i];
        unsigned gen = *rel;
        __threadfence();
        unsigned old = atomicAdd(&g_ctr[i], 1u);
        if (old == NBLK - 1) {
            atomicExch(&g_ctr[i], 0u);
            __threadfence();
            atomicAdd(&g_rel[i], 1u);
        } else {
            while (*rel == gen) { }
        }
    }
    __syncthreads();
}

// Monotone packing: larger viol wins; ties -> smaller index wins.
__device__ __forceinline__ ull packkey(float v, int idx) {
    unsigned u = __float_as_uint(v);
    u = (u & 0x80000000u) ? ~u : (u | 0x80000000u);
    return (((ull)u) << 32) | (unsigned)(0xFFFF - idx);
}

__device__ __forceinline__ float unpack_sum(ull a) {
    return __uint_as_float((unsigned)(a & 0xffffffffull)) +
           __uint_as_float((unsigned)(a >> 32));
}

__global__ __launch_bounds__(NTHR, 1)
void k_fused(const float* __restrict__ x, const float* __restrict__ W,
             const float* __restrict__ bias, float* __restrict__ out) {
    __shared__ union {
        float xs[8][256];                 // GEMM: x tile
        float comb[256][8];               // GEMM: fh-combine
        float sq[4][256];                 // qnode: q_split rows
        float red[4][4][NC];              // ga: warp partials
        float an[512];                    // clip: a_node
        struct {                          // scan (47,140 B)
            float ga[NNODE * NC];
            float ag[NNODE];
            int   kk[NNODE];
            ull   part[16];
        } scan;
    } sm;

    const int tid = threadIdx.x;
    const int bb  = blockIdx.x;

    // ============ Phase T: interleave-transpose W -> d_wt2[f0][s] ============
    {
        const int f0 = bb;                 // 0..127, covers f = 4*f0..4*f0+3
        if (tid < 256) {
            float4 v = make_float4(0.f, 0.f, 0.f, 0.f);
            if (tid < NSPLIT) {
                v.x = W[(4 * f0 + 0) * NSPLIT + tid];
                v.y = W[(4 * f0 + 1) * NSPLIT + tid];
                v.z = W[(4 * f0 + 2) * NSPLIT + tid];
                v.w = W[(4 * f0 + 3) * NSPLIT + tid];
            }
            d_wt2[f0 * 256 + tid] = v;
        }
    }
    grid_bar(0);

    // ============ Phase G: GEMM partials (block = 8 rows x K-half) ============
    {
        const int rb = bb >> 1, h = bb & 1;
        const int b0 = rb * 8;
        const int f0glob = h * 256;
        for (int i = tid; i < 8 * 256; i += NTHR)
            sm.xs[i >> 8][i & 255] = x[(b0 + (i >> 8)) * FEAT + f0glob + (i & 255)];
        __syncthreads();

        const int s  = tid & 255;
        const int fh = tid >> 8;

        unsigned int xsm;
        asm("{ .reg .u64 t; cvta.to.shared.u64 t, %1; cvt.u32.u64 %0, t; }"
            : "=r"(xsm) : "l"((void*)sm.xs));
        const unsigned int xbase = xsm + fh * 512;   // xs[0][fh*128] in bytes

        ull a01[8], a23[8];
        #pragma unroll
        for (int r = 0; r < 8; r++) { a01[r] = 0ull; a23[r] = 0ull; }

        const float4* wp = d_wt2 + (h * 64 + fh * 32) * 256 + s;
        #pragma unroll 4
        for (int j = 0; j < 32; j++) {
            ull w01, w23;
            asm("ld.global.v2.b64 {%0,%1},[%2];"
                : "=l"(w01), "=l"(w23) : "l"(wp + j * 256));
            const unsigned int ja = xbase + j * 16;
            #pragma unroll
            for (int r = 0; r < 8; r++) {
                ull x01, x23;
                asm("ld.shared.v2.b64 {%0,%1},[%2];"
                    : "=l"(x01), "=l"(x23) : "r"(ja + r * 1024));
                asm("fma.rn.f32x2 %0,%1,%2,%0;" : "+l"(a01[r]) : "l"(w01), "l"(x01));
                asm("fma.rn.f32x2 %0,%1,%2,%0;" : "+l"(a23[r]) : "l"(w23), "l"(x23));
            }
        }
        float partial[8];
        #pragma unroll
        for (int r = 0; r < 8; r++)
            partial[r] = unpack_sum(a01[r]) + unpack_sum(a23[r]);

        __syncthreads();
        if (fh == 1 && s < NSPLIT) {
            #pragma unroll
            for (int r = 0; r < 8; r++) sm.comb[s][r] = partial[r];
        }
        __syncthreads();
        if (fh == 0 && s < NSPLIT) {
            #pragma unroll
            for (int r = 0; r < 8; r++)
                d_part[h][b0 + r][s] = partial[r] + sm.comb[s][r];
        }
    }
    grid_bar(1);

    // ============ Phase Q: q_node tree-min (block = 4 rows) ============
    {
        const int b0 = bb * 4;
        for (int i = tid; i < 4 * 256; i += NTHR) {
            int r = i >> 8, c = i & 255;
            if (c < NSPLIT)
                sm.sq[r][c] = d_part[0][b0 + r][c] + d_part[1][b0 + r][c] + bias[c];
        }
        __syncthreads();
        const int n = tid;
        if (n < NNODE) {
            float qv[4];
            #pragma unroll
            for (int r = 0; r < 4; r++) {
                float m = 1.0f;
                int a = n;
                while (a > 0) {
                    int p = (a - 1) >> 1;
                    float q = sm.sq[r][p];
                    m = fminf(m, (a == 2 * p + 1) ? -q : q);
                    a = p;
                }
                qv[r] = m;
                d_qrelu[(b0 + r) * NNODE + n] = fmaxf(m, 0.0f);
            }
            d_qT4[n * 128 + (b0 >> 2)] = make_float4(qv[0], qv[1], qv[2], qv[3]);
        }
    }
    grid_bar(2);

    // ============ Phase GA: g_a table (block = 4 nodes) ============
    {
        const float* qT = (const float*)d_qT4;   // [n][b], raw q
        const int sub = tid >> 7;
        const int n = bb * 4 + sub;
        const int bl = tid & 127;
        float acc[NC];
        #pragma unroll
        for (int c = 0; c < NC; c++) acc[c] = 0.f;
        if (n < NNODE) {
            #pragma unroll
            for (int j = 0; j < 4; j++) {
                float v = qT[n * BATCH + bl + j * 128];
                float qn5 = v + 0.5f;
                #pragma unroll
                for (int c = 0; c < NC; c++) {
                    float ac = c * 0.05f;
                    float d = ac - qn5;
                    acc[c] += (ac <= qn5) ? d * d : 0.0f;
                }
            }
        }
        #pragma unroll
        for (int c = 0; c < NC; c++) {
            #pragma unroll
            for (int off = 16; off; off >>= 1)
                acc[c] += __shfl_xor_sync(0xffffffffu, acc[c], off);
        }
        if ((tid & 31) == 0) {
            #pragma unroll
            for (int c = 0; c < NC; c++) sm.red[sub][(tid >> 5) & 3][c] = acc[c];
        }
        __syncthreads();
        if (bl < NC && n < NNODE) {
            int c = bl;
            float s = sm.red[sub][0][c] + sm.red[sub][1][c] + sm.red[sub][2][c] + sm.red[sub][3][c];
            float ac = c * 0.05f;
            d_ga[n * NC + c] = 0.5f * ac * ac + 0.5f * s;
        }
    }
    grid_bar(3);

    // ============ Phase S: isotonic merge scan (block 0 only) ============
    if (bb == 0) {
        float ai_last = 0.0f;
        for (int i = tid; i < NNODE * NC; i += NTHR)
            sm.scan.ga[i] = d_ga[i];
        __syncthreads();
        if (tid < NNODE) {
            sm.scan.kk[tid] = 0;
            const float* gn = &sm.scan.ga[tid * NC];
            float xv[NC]; float m = -1e30f;
            #pragma unroll
            for (int c = 0; c < NC; c++) { xv[c] = -100.0f * gn[c]; m = fmaxf(m, xv[c]); }
            float num = 0.f, den = 0.f;
            #pragma unroll
            for (int c = 0; c < NC; c++) { float e = expf(xv[c] - m); num += (c * 0.05f) * e; den += e; }
            sm.scan.ag[tid] = num / den;
        }
        __syncthreads();

        const ull THRESH = packkey(1e-8f, 0);
        const int wid = tid >> 5, lane = tid & 31;

        for (int it = 0; it < NNODE + 1; it++) {
            float viol = -1e30f;
            if (tid < NNODE) {
                float ai, ap;
                if (tid == 0) { ai = sm.scan.ag[0]; ap = 1.0f; }
                else {
                    int pi = (tid - 1) >> 1;
                    float ki = (float)sm.scan.kk[tid];
                    ai = (1.0f - ki) * sm.scan.ag[tid] + ki * sm.scan.ag[pi];
                    if (pi == 0) ap = sm.scan.ag[0];
                    else {
                        int gp = (pi - 1) >> 1;
                        float kp = (float)sm.scan.kk[pi];
                        ap = (1.0f - kp) * sm.scan.ag[pi] + kp * sm.scan.ag[gp];
                    }
                }
                ai_last = ai;
                viol = ai - ap;
            }
            ull key = packkey(viol, tid);
            #pragma unroll
            for (int off = 16; off; off >>= 1) {
                ull o = __shfl_xor_sync(0xffffffffu, key, off);
                if (o > key) key = o;
            }
            if (lane == 0) sm.scan.part[wid] = key;
            __syncthreads();
            ull best = sm.scan.part[0];
            #pragma unroll
            for (int w = 1; w < 16; w++) { ull o = sm.scan.part[w]; if (o > best) best = o; }
            int t = 0xFFFF - (int)(best & 0xFFFFull);
            if (best > THRESH || t == 0) break;   // fixed point

            int p = (t - 1) >> 1;
            float newag = 0.f;
            int g = -1, kt_old = 0;
            if (wid < 2) {
                g = wid ? t : p;
                int l = 2 * g + 1;
                int kg_i = sm.scan.kk[g];
                if (wid == 1) kt_old = kg_i;
                float kg = (float)kg_i + (g == t ? 1.0f : 0.0f);
                float kl = (l < NNODE) ? ((float)sm.scan.kk[l] + (l == t ? 1.0f : 0.0f)) : 0.0f;
                float kr = (l + 1 < NNODE) ? ((float)sm.scan.kk[l + 1] + (l + 1 == t ? 1.0f : 0.0f)) : 0.0f;
                float xval = -1e30f;
                if (lane < NC) {
                    float gg = (1.0f - kg) * sm.scan.ga[g * NC + lane];
                    if (l < NNODE)     gg += kl * sm.scan.ga[l * NC + lane];
                    if (l + 1 < NNODE) gg += kr * sm.scan.ga[(l + 1) * NC + lane];
                    xval = -100.0f * gg;
                }
                float m = xval;
                #pragma unroll
                for (int off = 16; off; off >>= 1)
                    m = fmaxf(m, __shfl_xor_sync(0xffffffffu, m, off));
                float e = (lane < NC) ? expf(xval - m) : 0.0f;
                float num = (lane * 0.05f) * e;
                float den = e;
                #pragma unroll
                for (int off = 16; off; off >>= 1) {
                    num += __shfl_xor_sync(0xffffffffu, num, off);
                    den += __shfl_xor_sync(0xffffffffu, den, off);
                }
                newag = num / den;
            }
            __syncthreads();
            if (wid < 2 && lane == 0) sm.scan.ag[g] = newag;
            if (wid == 1 && lane == 0) sm.scan.kk[t] = kt_old + 1;
            __syncthreads();
        }
        if (tid < NNODE) d_anode[tid] = ai_last;
    }
    grid_bar(4);

    // ============ Phase C: clip epilogue ============
    {
        if (tid < NNODE) sm.an[tid] = d_anode[tid];
        __syncthreads();
        const int b0 = bb * 4;
        for (int i = tid; i < 4 * 512; i += NTHR) {
            int r = i >> 9, n = i & 511;
            if (n < NNODE) {
                int idx = (b0 + r) * NNODE + n;
                out[idx] = fminf(d_qrelu[idx], sm.an[n]);
            }
        }
    }
}

extern "C" void kernel_launch(void* const* d_in, const int* in_sizes, int n_in,
                              void* d_out, int out_size) {
    const float* x = (const float*)d_in[0];
    const float* W = (const float*)d_in[1];
    const float* b = (const float*)d_in[2];
    // d_in[3] = max_depth (fixed = 8 for this problem's shapes)
    k_fused<<<NBLK, NTHR>>>(x, W, b, (float*)d_out);
}